// round 5
// baseline (speedup 1.0000x reference)
#include <cuda_runtime.h>
#include <cuda_fp16.h>
#include <math.h>

#define DIM (1u << 18)
#define CELLS (1u << 17)
#define BATCH 64

typedef unsigned long long pk;  // packed f32x2 (lane0 = low word = even amp)

// fp16 SoA planes, ping-pong. 4 x 32 MB static scratch.
__device__ __half2 g_x0[BATCH * CELLS];
__device__ __half2 g_y0[BATCH * CELLS];
__device__ __half2 g_x1[BATCH * CELLS];
__device__ __half2 g_y1[BATCH * CELLS];
// Readout diagonal dd[x] (CNOT perm + (c^2)^108 + 1/256 folded in).
__device__ __align__(8) float g_dd[DIM];

#define TAU 0.05004170837554f  // tan(0.05); gate A/c^2 = I + tau*(..) + tau^2*(..)

__device__ __forceinline__ pk pack2(float lo, float hi) {
    pk r; asm("mov.b64 %0,{%1,%2};" : "=l"(r) : "f"(lo), "f"(hi)); return r;
}
__device__ __forceinline__ void unpack2(pk p, float& lo, float& hi) {
    asm("mov.b64 {%0,%1},%2;" : "=f"(lo), "=f"(hi) : "l"(p));
}
__device__ __forceinline__ pk fma2(pk a, pk b, pk c) {
    pk d; asm("fma.rn.f32x2 %0,%1,%2,%3;" : "=l"(d) : "l"(a), "l"(b), "l"(c)); return d;
}
__device__ __forceinline__ pk mul2(pk a, pk b) {
    pk d; asm("mul.rn.f32x2 %0,%1,%2;" : "=l"(d) : "l"(a), "l"(b)); return d;
}
__device__ __forceinline__ pk swap2(pk p) { float lo, hi; unpack2(p, lo, hi); return pack2(hi, lo); }

struct KC { pk Tp, Tn, T2p, T2n; };
__device__ __forceinline__ KC mkKC() {
    const float t = TAU, t2 = TAU * TAU;
    KC k; k.Tp = pack2(t, t); k.Tn = pack2(-t, -t);
    k.T2p = pack2(t2, t2); k.T2n = pack2(-t2, -t2); return k;
}

// Two independent scaled butterflies (one per SIMD lane), 12 fma2.
__device__ __forceinline__ void bfly2t(pk& Xa, pk& Ya, pk& Xb, pk& Yb, const KC& k) {
    pk nXa = fma2(Yb, k.Tp, fma2(Xb, k.Tn, fma2(Ya, k.T2n, Xa)));
    pk nYa = fma2(Yb, k.Tn, fma2(Xb, k.Tn, fma2(Xa, k.T2p, Ya)));
    pk nXb = fma2(Xa, k.Tp, fma2(Ya, k.Tp, fma2(Yb, k.T2p, Xb)));
    pk nYb = fma2(Xa, k.Tn, fma2(Ya, k.Tp, fma2(Xb, k.T2n, Yb)));
    Xa = nXa; Ya = nYa; Xb = nXb; Yb = nYb;
}

// Gate on 3 register-index bits of an 8-pack array.
__device__ __forceinline__ void clean3(pk X[8], pk Y[8], const KC& k) {
#pragma unroll
    for (int bit = 0; bit < 3; bit++)
#pragma unroll
        for (int m = 0; m < 8; m++)
            if (!(m & (1 << bit))) {
                const int n = m | (1 << bit);
                bfly2t(X[m], Y[m], X[n], Y[n], k);
            }
}

// Gate on global bit 0 (the SIMD lane inside the pack).
__device__ __forceinline__ void bflyL(pk& X, pk& Y, const KC& k) {
    const float t = TAU, t2 = TAU * TAU;
    const pk Tm = pack2(-t, t), T2m = pack2(-t2, t2), T2m2 = pack2(t2, -t2);
    pk sX = swap2(X), sY = swap2(Y);
    pk nX = fma2(sY, k.Tp, fma2(sX, Tm, fma2(Y, T2m, X)));
    pk nY = fma2(sY, Tm, fma2(sX, k.Tn, fma2(X, T2m2, Y)));
    X = nX; Y = nY;
}

// CNOT-ring label permutation (wire w <-> bit 17-w). Linear over XOR.
__device__ __forceinline__ unsigned cmap(unsigned x) {
    unsigned sx = x;
    sx ^= sx >> 1; sx ^= sx >> 2; sx ^= sx >> 4; sx ^= sx >> 8; sx ^= sx >> 16;
    return (sx & 0x1FFFFu) | (((sx ^ (x >> 17)) & 1u) << 17);
}

#define PAD6(c) ((c) + ((c) >> 6))

// ---------------------------------------------------------------------------
// LO pass: gates on x bits 0..12. Slab = 4096 cells. 512 threads x 8 packs.
// Phases: lane bit + cell bits 9..11 | 6..8 | 3..5 | 0..2 (3 smem transposes).
// ---------------------------------------------------------------------------
__global__ void __launch_bounds__(512, 2) pass_lo(__half2* __restrict__ px,
                                                  __half2* __restrict__ py,
                                                  const float* __restrict__ re,
                                                  const float* __restrict__ im,
                                                  int first) {
    extern __shared__ pk sm[];
    pk* sx = sm;          // 4160 pk
    pk* sy = sm + 4160;   // 4160 pk
    const int t = threadIdx.x;  // 9 bits
    const unsigned b = blockIdx.x >> 5, hi = blockIdx.x & 31;
    const size_t cb = ((size_t)b << 17) | ((size_t)hi << 12);
    const KC k = mkKC();

    pk X[8], Y[8];
    // layout0: c = (r<<9) | t ; reg = cell bits 9..11 (x bits 10..12)
    if (first) {
        const pk s16 = pack2(16.0f, 16.0f);
#pragma unroll
        for (int r = 0; r < 8; r++) {
            const size_t a = (cb + (unsigned)((r << 9) | t)) * 2;
            X[r] = mul2(*(const pk*)(re + a), s16);
            Y[r] = mul2(*(const pk*)(im + a), s16);
        }
    } else {
#pragma unroll
        for (int r = 0; r < 8; r++) {
            const size_t c = cb + (unsigned)((r << 9) | t);
            float2 fx = __half22float2(px[c]);
            float2 fy = __half22float2(py[c]);
            X[r] = pack2(fx.x, fx.y);
            Y[r] = pack2(fy.x, fy.y);
        }
    }

#pragma unroll
    for (int m = 0; m < 8; m++) bflyL(X[m], Y[m], k);   // x bit 0
    clean3(X, Y, k);                                     // x bits 10..12

    const unsigned a3 = t >> 6, b6 = t & 63;
    // T1: layout0 -> layout3 (c = a3<<9 | r<<6 | b6; reg = cell bits 6..8)
#pragma unroll
    for (int r = 0; r < 8; r++) { const unsigned c = (r << 9) | t; sx[PAD6(c)] = X[r]; sy[PAD6(c)] = Y[r]; }
    __syncthreads();
#pragma unroll
    for (int r = 0; r < 8; r++) { const unsigned c = (a3 << 9) | (r << 6) | b6; X[r] = sx[PAD6(c)]; Y[r] = sy[PAD6(c)]; }
    clean3(X, Y, k);                                     // x bits 7..9
    __syncthreads();

    // T2: layout3 -> layout2 (c = b6<<6 | r<<3 | a3; reg = cell bits 3..5)
#pragma unroll
    for (int r = 0; r < 8; r++) { const unsigned c = (a3 << 9) | (r << 6) | b6; sx[PAD6(c)] = X[r]; sy[PAD6(c)] = Y[r]; }
    __syncthreads();
#pragma unroll
    for (int r = 0; r < 8; r++) { const unsigned c = (b6 << 6) | (r << 3) | a3; X[r] = sx[PAD6(c)]; Y[r] = sy[PAD6(c)]; }
    clean3(X, Y, k);                                     // x bits 4..6
    __syncthreads();

    // T3: layout2 -> layout1 (c = t<<3 | r; reg = cell bits 0..2)
#pragma unroll
    for (int r = 0; r < 8; r++) { const unsigned c = (b6 << 6) | (r << 3) | a3; sx[PAD6(c)] = X[r]; sy[PAD6(c)] = Y[r]; }
    __syncthreads();
#pragma unroll
    for (int r = 0; r < 8; r++) { const unsigned c = ((unsigned)t << 3) | r; X[r] = sx[PAD6(c)]; Y[r] = sy[PAD6(c)]; }
    clean3(X, Y, k);                                     // x bits 1..3

    // store: 8 consecutive cells per thread -> 2 x 16B per plane
    unsigned hx[8], hy[8];
#pragma unroll
    for (int r = 0; r < 8; r++) {
        float a0, a1;
        unpack2(X[r], a0, a1); __half2 h = __floats2half2_rn(a0, a1); hx[r] = *(unsigned*)&h;
        unpack2(Y[r], a0, a1); h = __floats2half2_rn(a0, a1); hy[r] = *(unsigned*)&h;
    }
    uint4* px4 = (uint4*)(px + cb + ((unsigned)t << 3));
    uint4* py4 = (uint4*)(py + cb + ((unsigned)t << 3));
    px4[0] = make_uint4(hx[0], hx[1], hx[2], hx[3]);
    px4[1] = make_uint4(hx[4], hx[5], hx[6], hx[7]);
    py4[0] = make_uint4(hy[0], hy[1], hy[2], hy[3]);
    py4[1] = make_uint4(hy[4], hy[5], hy[6], hy[7]);
}

// ---------------------------------------------------------------------------
// HI gates (x bits 13..17): cell bits 12..14 = reg r, 15 = L3, 16 = L4.
// ---------------------------------------------------------------------------
#define SHFLGATE(DIST, SBIT)                                                          \
    {                                                                                 \
        const float e_ = (SBIT) ? TAU : -TAU;                                         \
        const pk eT = pack2(e_, e_), eT2 = pack2(e_ * TAU, e_ * TAU),                 \
                 eT2n = pack2(-e_ * TAU, -e_ * TAU);                                  \
        _Pragma("unroll")                                                             \
        for (int r = 0; r < 8; r++) {                                                 \
            pk pX = __shfl_xor_sync(0xffffffffu, X[r], (DIST));                       \
            pk pY = __shfl_xor_sync(0xffffffffu, Y[r], (DIST));                       \
            pk nX = fma2(pY, k.Tp, fma2(pX, eT, fma2(Y[r], eT2, X[r])));              \
            pk nY = fma2(pY, eT, fma2(pX, k.Tn, fma2(X[r], eT2n, Y[r])));             \
            X[r] = nX; Y[r] = nY;                                                     \
        }                                                                             \
    }

__device__ __forceinline__ void hi_load_gates(const __half2* __restrict__ sx,
                                              const __half2* __restrict__ sy,
                                              size_t bb, unsigned clo, int L3, int L4,
                                              const KC& k, pk X[8], pk Y[8]) {
#pragma unroll
    for (int r = 0; r < 8; r++) {
        const size_t c = bb + (clo | ((unsigned)r << 12));
        float2 fx = __half22float2(sx[c]);
        float2 fy = __half22float2(sy[c]);
        X[r] = pack2(fx.x, fx.y);
        Y[r] = pack2(fy.x, fy.y);
    }
    clean3(X, Y, k);       // x bits 13..15
    SHFLGATE(8, L3);       // x bit 16
    SHFLGATE(16, L4);      // x bit 17
}

// ---------------------------------------------------------------------------
// HI pass + CNOT permutation folded into the store (partner via shfl 24 + prmt).
// ---------------------------------------------------------------------------
__global__ void __launch_bounds__(256, 3) pass_hi(const __half2* __restrict__ sx,
                                                  const __half2* __restrict__ sy,
                                                  __half2* __restrict__ dx,
                                                  __half2* __restrict__ dy) {
    const int t = threadIdx.x, L = t & 31, W = t >> 5;
    const int L3 = (L >> 3) & 1, L4 = (L >> 4) & 1;
    const unsigned b = blockIdx.x >> 6, mid = blockIdx.x & 63;
    const size_t bb = (size_t)b << 17;
    const unsigned clo = (mid << 6) | ((unsigned)W << 3) | (unsigned)(L & 7)
                       | ((unsigned)L3 << 15) | ((unsigned)L4 << 16);
    const KC k = mkKC();

    pk X[8], Y[8];
    hi_load_gates(sx, sy, bb, clo, L3, L4, k, X, Y);

    unsigned hx[8], hy[8];
#pragma unroll
    for (int r = 0; r < 8; r++) {
        float a0, a1;
        unpack2(X[r], a0, a1); __half2 h = __floats2half2_rn(a0, a1); hx[r] = *(unsigned*)&h;
        unpack2(Y[r], a0, a1); h = __floats2half2_rn(a0, a1); hy[r] = *(unsigned*)&h;
    }

    const unsigned cB = cmap(clo << 1);
    const int pb = __popc(clo) & 1;
#pragma unroll
    for (int r = 0; r < 8; r++) {
        const unsigned phx = __shfl_xor_sync(0xffffffffu, hx[r], 24);
        const unsigned phy = __shfl_xor_sync(0xffffffffu, hy[r], 24);
        const int pr = pb ^ (__popc((unsigned)r) & 1);
        const unsigned ctrl = pr ? 0x5432u : 0x7610u;
        const unsigned ox = __byte_perm(hx[r], phx, ctrl);
        const unsigned oy = __byte_perm(hy[r], phy, ctrl);
        const unsigned y = cB ^ cmap((unsigned)r << 13) ^ (pr ? 0x20001u : 0u);
        const size_t dc = bb + (y >> 1);
        dx[dc] = *(const __half2*)&ox;
        dy[dc] = *(const __half2*)&oy;
    }
}

// ---------------------------------------------------------------------------
// Final: HI gates of layer 3 + weighted |.|^2 readout (perm + scales in dd).
// ---------------------------------------------------------------------------
__global__ void __launch_bounds__(256, 3) pass_reduce(const __half2* __restrict__ sx,
                                                      const __half2* __restrict__ sy,
                                                      float* __restrict__ out) {
    const int t = threadIdx.x, L = t & 31, W = t >> 5;
    const int L3 = (L >> 3) & 1, L4 = (L >> 4) & 1;
    const unsigned b = blockIdx.x >> 6, mid = blockIdx.x & 63;
    const size_t bb = (size_t)b << 17;
    const unsigned clo = (mid << 6) | ((unsigned)W << 3) | (unsigned)(L & 7)
                       | ((unsigned)L3 << 15) | ((unsigned)L4 << 16);
    const KC k = mkKC();

    pk X[8], Y[8];
    hi_load_gates(sx, sy, bb, clo, L3, L4, k, X, Y);

    pk acc = pack2(0.0f, 0.0f);
#pragma unroll
    for (int r = 0; r < 8; r++) {
        const unsigned c = clo | ((unsigned)r << 12);
        const pk dpk = *(const pk*)(g_dd + ((size_t)c << 1));
        pk p2 = fma2(Y[r], Y[r], mul2(X[r], X[r]));
        acc = fma2(p2, dpk, acc);
    }
    float a0, a1; unpack2(acc, a0, a1);
    float a = a0 + a1;
#pragma unroll
    for (int o = 16; o; o >>= 1) a += __shfl_xor_sync(0xffffffffu, a, o);
    __shared__ float ws[8];
    if (L == 0) ws[W] = a;
    __syncthreads();
    if (t < 8) {
        float s = ws[t];
#pragma unroll
        for (int o = 4; o; o >>= 1) s += __shfl_xor_sync(0xffu, s, o);
        if (t == 0) atomicAdd(out + b, s);
    }
}

// ---------------------------------------------------------------------------
// Init dd[] and out[b] = head_b (out is poisoned before each timed run).
// ---------------------------------------------------------------------------
__global__ void __launch_bounds__(256) init_kernel(const float* __restrict__ hw,
                                                   const float* __restrict__ hb,
                                                   float* __restrict__ out, float scale) {
    const unsigned x = blockIdx.x * 256u + threadIdx.x;
    if (x < DIM) {
        const unsigned y = cmap(x);
        float d = 0.0f;
#pragma unroll
        for (int w = 0; w < 18; w++)
            d += hw[w] * (((y >> (17 - w)) & 1u) ? -1.0f : 1.0f);
        g_dd[x] = d * scale;
    }
    if (x < BATCH) out[x] = hb[0];
}

extern "C" void kernel_launch(void* const* d_in, const int* in_sizes, int n_in,
                              void* d_out, int out_size) {
    (void)in_sizes; (void)n_in; (void)out_size;
    const float* re = (const float*)d_in[0];
    const float* im = (const float*)d_in[1];
    const float* hw = (const float*)d_in[2];
    const float* hb = (const float*)d_in[3];
    float* out = (float*)d_out;

    __half2 *x0, *y0, *x1, *y1;
    cudaGetSymbolAddress((void**)&x0, g_x0);
    cudaGetSymbolAddress((void**)&y0, g_y0);
    cudaGetSymbolAddress((void**)&x1, g_x1);
    cudaGetSymbolAddress((void**)&y1, g_y1);

    const int smemLO = 2 * 4160 * (int)sizeof(pk);  // 66560 B
    cudaFuncSetAttribute(pass_lo, cudaFuncAttributeMaxDynamicSharedMemorySize, smemLO);

    // deferred gate scale: (c^2)^108 for probs; /256 for the x16 input scaling
    const float scale = (float)(pow(0.9975020826390129, 108.0) / 256.0);

    const int gridLO = BATCH * 32;   // 2048 CTAs x 512 thr
    const int gridHI = BATCH * 64;   // 4096 CTAs x 256 thr

    init_kernel<<<DIM / 256, 256>>>(hw, hb, out, scale);

    // Layer 1
    pass_lo<<<gridLO, 512, smemLO>>>(x0, y0, re, im, 1);
    pass_hi<<<gridHI, 256>>>(x0, y0, x1, y1);
    // Layer 2
    pass_lo<<<gridLO, 512, smemLO>>>(x1, y1, re, im, 0);
    pass_hi<<<gridHI, 256>>>(x1, y1, x0, y0);
    // Layer 3
    pass_lo<<<gridLO, 512, smemLO>>>(x0, y0, re, im, 0);
    pass_reduce<<<gridHI, 256>>>(x0, y0, out);
}